// round 3
// baseline (speedup 1.0000x reference)
#include <cuda_runtime.h>

// GAT 2-layer, N<=100000 nodes, E edges, F_in=16, H=4, C=8.
// Softmax computed WITHOUT max-shift (mathematically identical), so each layer
// needs only ONE edge pass:
//   acc[dst] += exp(e) * h[src]   (red.global.add.v4.f32)
//   den[dst] += exp(e)
// Self-loop contribution is the accumulator's initial value (plain store).
// edge_index arrives as int32 (harness narrows int64 inputs to int32).

#define NMAX 100000

__device__ float4 g_h1  [NMAX * 8];  // h1 [N,32]
__device__ float4 g_as1 [NMAX];      // a_src [N,4]
__device__ float4 g_ad1 [NMAX];      // a_dst [N,4]
__device__ float4 g_acc1[NMAX * 8];  // accum [N,32]
__device__ float4 g_den1[NMAX];      // denom [N,4]
__device__ float  g_h2  [NMAX];
__device__ float2 g_l2  [NMAX];      // {den2, acc2}

__device__ __forceinline__ void red_add_v4(float4* addr, float a, float b, float c, float d) {
    asm volatile("red.global.add.v4.f32 [%0], {%1,%2,%3,%4};"
                 :: "l"(addr), "f"(a), "f"(b), "f"(c), "f"(d) : "memory");
}
__device__ __forceinline__ void red_add_v2(float2* addr, float a, float b) {
    asm volatile("red.global.add.v2.f32 [%0], {%1,%2};"
                 :: "l"(addr), "f"(a), "f"(b) : "memory");
}

__device__ __forceinline__ float lrelu(float e) { return fmaxf(e, 0.2f * e); }

// ---------------------------------------------------------------------------
// K1: per-node: h1 = x@W1, attention logit halves, self-loop init of acc/den.
// ---------------------------------------------------------------------------
__global__ void k_node1(const float* __restrict__ x, const float* __restrict__ W1,
                        const float* __restrict__ att_s, const float* __restrict__ att_d,
                        int N) {
    __shared__ float sW[512];
    __shared__ float sas[32], sad[32];
    for (int t = threadIdx.x; t < 512; t += blockDim.x) sW[t] = W1[t];
    if (threadIdx.x < 32) { sas[threadIdx.x] = att_s[threadIdx.x]; sad[threadIdx.x] = att_d[threadIdx.x]; }
    __syncthreads();

    int i = blockIdx.x * blockDim.x + threadIdx.x;
    if (i >= N) return;

    float xv[16];
    const float4* xr = reinterpret_cast<const float4*>(x + (size_t)i * 16);
    #pragma unroll
    for (int q = 0; q < 4; q++) {
        float4 v = xr[q];
        xv[4*q] = v.x; xv[4*q+1] = v.y; xv[4*q+2] = v.z; xv[4*q+3] = v.w;
    }

    float h[32];
    #pragma unroll
    for (int c = 0; c < 32; c++) h[c] = 0.f;
    #pragma unroll
    for (int k = 0; k < 16; k++) {
        float xk = xv[k];
        #pragma unroll
        for (int c = 0; c < 32; c++) h[c] = fmaf(xk, sW[k*32 + c], h[c]);
    }

    float as[4], ad[4];
    #pragma unroll
    for (int hh = 0; hh < 4; hh++) {
        float sa = 0.f, sd = 0.f;
        #pragma unroll
        for (int c = 0; c < 8; c++) {
            sa = fmaf(h[hh*8 + c], sas[hh*8 + c], sa);
            sd = fmaf(h[hh*8 + c], sad[hh*8 + c], sd);
        }
        as[hh] = sa; ad[hh] = sd;
    }

    #pragma unroll
    for (int q = 0; q < 8; q++)
        g_h1[(size_t)i * 8 + q] = make_float4(h[4*q], h[4*q+1], h[4*q+2], h[4*q+3]);
    g_as1[i] = make_float4(as[0], as[1], as[2], as[3]);
    g_ad1[i] = make_float4(ad[0], ad[1], ad[2], ad[3]);

    // self-loop: e = lrelu(as+ad); initializes accumulators (also zeroes them)
    float ex[4];
    #pragma unroll
    for (int hh = 0; hh < 4; hh++) ex[hh] = __expf(lrelu(as[hh] + ad[hh]));
    g_den1[i] = make_float4(ex[0], ex[1], ex[2], ex[3]);

    #pragma unroll
    for (int q = 0; q < 8; q++) {
        float e = ex[q >> 1];
        g_acc1[(size_t)i * 8 + q] = make_float4(e*h[4*q], e*h[4*q+1], e*h[4*q+2], e*h[4*q+3]);
    }
}

// ---------------------------------------------------------------------------
// K2: layer-1 edge pass: acc[dst] += exp(e)*h1[src]; den[dst] += exp(e)
// ---------------------------------------------------------------------------
__global__ void k_edge1(const int* __restrict__ ei, int E) {
    int i = blockIdx.x * blockDim.x + threadIdx.x;
    if (i >= E) return;
    int s = __ldg(ei + i);
    int d = __ldg(ei + E + i);

    float4 as = g_as1[s];
    float4 ad = g_ad1[d];
    float ex0 = __expf(lrelu(as.x + ad.x));
    float ex1 = __expf(lrelu(as.y + ad.y));
    float ex2 = __expf(lrelu(as.z + ad.z));
    float ex3 = __expf(lrelu(as.w + ad.w));

    red_add_v4(&g_den1[d], ex0, ex1, ex2, ex3);

    const float4* hv = &g_h1[(size_t)s * 8];
    float4* accb = &g_acc1[(size_t)d * 8];
    float exh[8] = {ex0, ex0, ex1, ex1, ex2, ex2, ex3, ex3};
    #pragma unroll
    for (int q = 0; q < 8; q++) {
        float4 v = hv[q];
        float e = exh[q];
        red_add_v4(accb + q, e*v.x, e*v.y, e*v.z, e*v.w);
    }
}

// ---------------------------------------------------------------------------
// K3: per-node: finalize layer1 (normalize + bias + elu), h2 = out1@W2,
//     self-loop init of layer-2 accumulators.
// ---------------------------------------------------------------------------
__global__ void k_node2(const float* __restrict__ b1, const float* __restrict__ W2,
                        const float* __restrict__ as2p, const float* __restrict__ ad2p,
                        int N) {
    __shared__ float sb1[32], sW2[32];
    if (threadIdx.x < 32) { sb1[threadIdx.x] = b1[threadIdx.x]; sW2[threadIdx.x] = W2[threadIdx.x]; }
    __syncthreads();

    int i = blockIdx.x * blockDim.x + threadIdx.x;
    if (i >= N) return;

    float4 dv = g_den1[i];
    float invd[4] = {1.f / (dv.x + 1e-16f), 1.f / (dv.y + 1e-16f),
                     1.f / (dv.z + 1e-16f), 1.f / (dv.w + 1e-16f)};

    float h2 = 0.f;
    #pragma unroll
    for (int q = 0; q < 8; q++) {
        float4 v = g_acc1[(size_t)i * 8 + q];
        float id = invd[q >> 1];
        float o0 = v.x * id + sb1[4*q+0];
        float o1 = v.y * id + sb1[4*q+1];
        float o2 = v.z * id + sb1[4*q+2];
        float o3 = v.w * id + sb1[4*q+3];
        o0 = o0 > 0.f ? o0 : (__expf(o0) - 1.f);
        o1 = o1 > 0.f ? o1 : (__expf(o1) - 1.f);
        o2 = o2 > 0.f ? o2 : (__expf(o2) - 1.f);
        o3 = o3 > 0.f ? o3 : (__expf(o3) - 1.f);
        h2 = fmaf(o0, sW2[4*q+0], h2);
        h2 = fmaf(o1, sW2[4*q+1], h2);
        h2 = fmaf(o2, sW2[4*q+2], h2);
        h2 = fmaf(o3, sW2[4*q+3], h2);
    }
    g_h2[i] = h2;

    float asc = __ldg(as2p), adc = __ldg(ad2p);
    float ex = __expf(lrelu(h2 * asc + h2 * adc));
    g_l2[i] = make_float2(ex, ex * h2);
}

// ---------------------------------------------------------------------------
// K4: layer-2 edge pass
// ---------------------------------------------------------------------------
__global__ void k_edge2(const int* __restrict__ ei,
                        const float* __restrict__ as2p, const float* __restrict__ ad2p,
                        int E) {
    int i = blockIdx.x * blockDim.x + threadIdx.x;
    if (i >= E) return;
    int s = __ldg(ei + i);
    int d = __ldg(ei + E + i);
    float asc = __ldg(as2p), adc = __ldg(ad2p);
    float hs = g_h2[s];
    float hd = g_h2[d];
    float ex = __expf(lrelu(hs * asc + hd * adc));
    red_add_v2(&g_l2[d], ex, ex * hs);
}

// ---------------------------------------------------------------------------
// K5: finalize
// ---------------------------------------------------------------------------
__global__ void k_final(float* __restrict__ out, const float* __restrict__ b2, int N) {
    int i = blockIdx.x * blockDim.x + threadIdx.x;
    if (i >= N) return;
    float2 v = g_l2[i];
    out[i] = v.y / (v.x + 1e-16f) + __ldg(b2);
}

extern "C" void kernel_launch(void* const* d_in, const int* in_sizes, int n_in,
                              void* d_out, int out_size) {
    const float* x     = (const float*)d_in[0];
    const int*   ei    = (const int*)d_in[1];
    const float* W1    = (const float*)d_in[2];
    const float* att_s = (const float*)d_in[3];
    const float* att_d = (const float*)d_in[4];
    const float* b1    = (const float*)d_in[5];
    const float* W2    = (const float*)d_in[6];
    const float* as2   = (const float*)d_in[7];
    const float* ad2   = (const float*)d_in[8];
    const float* b2    = (const float*)d_in[9];
    float* out = (float*)d_out;

    int N = in_sizes[0] / 16;
    int E = in_sizes[1] / 2;

    const int TB = 256;
    int nb_n = (N + TB - 1) / TB;
    int nb_e = (E + TB - 1) / TB;

    k_node1<<<nb_n, TB>>>(x, W1, att_s, att_d, N);
    k_edge1<<<nb_e, TB>>>(ei, E);
    k_node2<<<nb_n, TB>>>(b1, W2, as2, ad2, N);
    k_edge2<<<nb_e, TB>>>(ei, as2, ad2, E);
    k_final<<<nb_n, TB>>>(out, b2, N);
}

// round 4
// speedup vs baseline: 1.4683x; 1.4683x over previous
#include <cuda_runtime.h>

// GAT 2-layer, N<=100000, F_in=16, H=4, C=8. Atomic-free aggregation:
// per-call counting sort of edges by dst (CSR) + one-warp-per-dst reduction.
// Softmax without max-shift (mathematically identical, logits are O(1)).

#define NMAX 100000
#define EMAX 3200000

__device__ float4 g_h1 [NMAX * 8];  // h1 [N,32]
__device__ float4 g_as1[NMAX];      // a_src [N,4]
__device__ float4 g_ad1[NMAX];      // a_dst [N,4]
__device__ float  g_h2 [NMAX];
__device__ int    g_cnt[NMAX];      // in-degree
__device__ int    g_rs [NMAX];      // row start (exclusive scan of cnt)
__device__ int    g_ofs[NMAX];      // scatter cursor (copy of rs)
__device__ int    g_src[EMAX];      // src ids grouped by dst
__device__ int    g_part[1024];     // scan partials

__device__ __forceinline__ float lrelu(float e) { return fmaxf(e, 0.2f * e); }

// --------------------------------------------------------------------------
__global__ void k_zero(int N) {
    int i = blockIdx.x * blockDim.x + threadIdx.x;
    if (i < N) g_cnt[i] = 0;
}

__global__ void k_hist(const int* __restrict__ ei, int E) {
    int i = blockIdx.x * blockDim.x + threadIdx.x;
    if (i < E) atomicAdd(&g_cnt[__ldg(ei + E + i)], 1);
}

// --------------------------------------------------------------------------
// Node features: h1 = x@W1, per-head logit halves as1/ad1.
// --------------------------------------------------------------------------
__global__ void k_node1(const float* __restrict__ x, const float* __restrict__ W1,
                        const float* __restrict__ att_s, const float* __restrict__ att_d,
                        int N) {
    __shared__ float sW[512];
    __shared__ float sas[32], sad[32];
    for (int t = threadIdx.x; t < 512; t += blockDim.x) sW[t] = W1[t];
    if (threadIdx.x < 32) { sas[threadIdx.x] = att_s[threadIdx.x]; sad[threadIdx.x] = att_d[threadIdx.x]; }
    __syncthreads();

    int i = blockIdx.x * blockDim.x + threadIdx.x;
    if (i >= N) return;

    float xv[16];
    const float4* xr = reinterpret_cast<const float4*>(x + (size_t)i * 16);
    #pragma unroll
    for (int q = 0; q < 4; q++) {
        float4 v = xr[q];
        xv[4*q] = v.x; xv[4*q+1] = v.y; xv[4*q+2] = v.z; xv[4*q+3] = v.w;
    }

    float h[32];
    #pragma unroll
    for (int c = 0; c < 32; c++) h[c] = 0.f;
    #pragma unroll
    for (int k = 0; k < 16; k++) {
        float xk = xv[k];
        #pragma unroll
        for (int c = 0; c < 32; c++) h[c] = fmaf(xk, sW[k*32 + c], h[c]);
    }

    float as[4], ad[4];
    #pragma unroll
    for (int hh = 0; hh < 4; hh++) {
        float sa = 0.f, sd = 0.f;
        #pragma unroll
        for (int c = 0; c < 8; c++) {
            sa = fmaf(h[hh*8 + c], sas[hh*8 + c], sa);
            sd = fmaf(h[hh*8 + c], sad[hh*8 + c], sd);
        }
        as[hh] = sa; ad[hh] = sd;
    }

    #pragma unroll
    for (int q = 0; q < 8; q++)
        g_h1[(size_t)i * 8 + q] = make_float4(h[4*q], h[4*q+1], h[4*q+2], h[4*q+3]);
    g_as1[i] = make_float4(as[0], as[1], as[2], as[3]);
    g_ad1[i] = make_float4(ad[0], ad[1], ad[2], ad[3]);
}

// --------------------------------------------------------------------------
// Two-level exclusive scan over g_cnt -> g_rs (N <= 1024*1024)
// --------------------------------------------------------------------------
__global__ void k_scan_block(int N) {
    __shared__ int sh[1024];
    int t = threadIdx.x;
    int i = blockIdx.x * 1024 + t;
    int v = (i < N) ? g_cnt[i] : 0;
    sh[t] = v;
    __syncthreads();
    #pragma unroll
    for (int off = 1; off < 1024; off <<= 1) {
        int add = (t >= off) ? sh[t - off] : 0;
        __syncthreads();
        sh[t] += add;
        __syncthreads();
    }
    if (i < N) g_rs[i] = sh[t] - v;          // exclusive
    if (t == 1023) g_part[blockIdx.x] = sh[t]; // block total
}

__global__ void k_scan_top(int NB) {
    __shared__ int sh[1024];
    int t = threadIdx.x;
    int v = (t < NB) ? g_part[t] : 0;
    sh[t] = v;
    __syncthreads();
    #pragma unroll
    for (int off = 1; off < 1024; off <<= 1) {
        int add = (t >= off) ? sh[t - off] : 0;
        __syncthreads();
        sh[t] += add;
        __syncthreads();
    }
    if (t < NB) g_part[t] = sh[t] - v;       // exclusive block offsets
}

__global__ void k_scan_add(int N) {
    int i = blockIdx.x * blockDim.x + threadIdx.x;
    if (i >= N) return;
    int v = g_rs[i] + g_part[i >> 10];
    g_rs[i] = v;
    g_ofs[i] = v;
}

__global__ void k_scatter(const int* __restrict__ ei, int E) {
    int i = blockIdx.x * blockDim.x + threadIdx.x;
    if (i >= E) return;
    int s = __ldg(ei + i);
    int d = __ldg(ei + E + i);
    int pos = atomicAdd(&g_ofs[d], 1);
    g_src[pos] = s;
}

// --------------------------------------------------------------------------
// Layer-1 reduction + full node epilogue. One warp per dst node.
// Lane = 8*g + j: group g in [0,4) handles every 4th edge, lane j handles
// feature components [4j, 4j+4) (head = j>>1).
// --------------------------------------------------------------------------
__global__ void k_reduce1(const float* __restrict__ b1, const float* __restrict__ W2,
                          const float* __restrict__ as2p, const float* __restrict__ ad2p,
                          int N) {
    int warp = threadIdx.x >> 5;
    int row = blockIdx.x * 8 + warp;
    if (row >= N) return;
    int lane = threadIdx.x & 31;
    int j = lane & 7;
    int g = lane >> 3;
    int hsel = j >> 1;

    int rs = g_rs[row];
    int re = rs + g_cnt[row];
    float4 ad = g_ad1[row];

    float4 acc = make_float4(0.f, 0.f, 0.f, 0.f);
    float dsum = 0.f;

    if (g == 0) {  // self loop
        float4 as = g_as1[row];
        float ex0 = __expf(lrelu(as.x + ad.x));
        float ex1 = __expf(lrelu(as.y + ad.y));
        float ex2 = __expf(lrelu(as.z + ad.z));
        float ex3 = __expf(lrelu(as.w + ad.w));
        float e = hsel == 0 ? ex0 : hsel == 1 ? ex1 : hsel == 2 ? ex2 : ex3;
        float4 hv = g_h1[(size_t)row * 8 + j];
        acc = make_float4(e*hv.x, e*hv.y, e*hv.z, e*hv.w);
        dsum = e;
    }

    for (int k = rs + g; k < re; k += 4) {
        int s = __ldg(&g_src[k]);
        float4 as = g_as1[s];
        float ex0 = __expf(lrelu(as.x + ad.x));
        float ex1 = __expf(lrelu(as.y + ad.y));
        float ex2 = __expf(lrelu(as.z + ad.z));
        float ex3 = __expf(lrelu(as.w + ad.w));
        float e = hsel == 0 ? ex0 : hsel == 1 ? ex1 : hsel == 2 ? ex2 : ex3;
        float4 hv = g_h1[(size_t)s * 8 + j];
        acc.x = fmaf(e, hv.x, acc.x);
        acc.y = fmaf(e, hv.y, acc.y);
        acc.z = fmaf(e, hv.z, acc.z);
        acc.w = fmaf(e, hv.w, acc.w);
        dsum += e;
    }

    // reduce across the 4 groups (lanes j, j+8, j+16, j+24)
    #pragma unroll
    for (int m = 8; m <= 16; m <<= 1) {
        acc.x += __shfl_xor_sync(0xFFFFFFFFu, acc.x, m);
        acc.y += __shfl_xor_sync(0xFFFFFFFFu, acc.y, m);
        acc.z += __shfl_xor_sync(0xFFFFFFFFu, acc.z, m);
        acc.w += __shfl_xor_sync(0xFFFFFFFFu, acc.w, m);
        dsum  += __shfl_xor_sync(0xFFFFFFFFu, dsum,  m);
    }

    // epilogue on lanes 0-7: normalize, +b1, elu, dot with W2
    float partial = 0.f;
    {
        float id = 1.f / (dsum + 1e-16f);
        float o0 = acc.x * id + __ldg(b1 + 4*j + 0);
        float o1 = acc.y * id + __ldg(b1 + 4*j + 1);
        float o2 = acc.z * id + __ldg(b1 + 4*j + 2);
        float o3 = acc.w * id + __ldg(b1 + 4*j + 3);
        o0 = o0 > 0.f ? o0 : (__expf(o0) - 1.f);
        o1 = o1 > 0.f ? o1 : (__expf(o1) - 1.f);
        o2 = o2 > 0.f ? o2 : (__expf(o2) - 1.f);
        o3 = o3 > 0.f ? o3 : (__expf(o3) - 1.f);
        partial  = o0 * __ldg(W2 + 4*j + 0);
        partial += o1 * __ldg(W2 + 4*j + 1);
        partial += o2 * __ldg(W2 + 4*j + 2);
        partial += o3 * __ldg(W2 + 4*j + 3);
    }
    #pragma unroll
    for (int m = 1; m <= 4; m <<= 1)
        partial += __shfl_xor_sync(0xFFFFFFFFu, partial, m);

    if (lane == 0) g_h2[row] = partial;
}

// --------------------------------------------------------------------------
// Layer-2 reduction: one warp per dst, fused finalize. 32 edges/iter.
// --------------------------------------------------------------------------
__global__ void k_reduce2(float* __restrict__ out,
                          const float* __restrict__ as2p, const float* __restrict__ ad2p,
                          const float* __restrict__ b2, int N) {
    int warp = threadIdx.x >> 5;
    int row = blockIdx.x * 8 + warp;
    if (row >= N) return;
    int lane = threadIdx.x & 31;

    float asc = __ldg(as2p), adc = __ldg(ad2p);
    float hd = g_h2[row];
    int rs = g_rs[row];
    int re = rs + g_cnt[row];

    float den = 0.f, num = 0.f;
    if (lane == 0) {  // self loop
        float ex = __expf(lrelu(hd * asc + hd * adc));
        den = ex; num = ex * hd;
    }
    for (int k = rs + lane; k < re; k += 32) {
        int s = __ldg(&g_src[k]);
        float hs = g_h2[s];
        float ex = __expf(lrelu(hs * asc + hd * adc));
        den += ex;
        num = fmaf(ex, hs, num);
    }
    #pragma unroll
    for (int m = 16; m >= 1; m >>= 1) {
        den += __shfl_xor_sync(0xFFFFFFFFu, den, m);
        num += __shfl_xor_sync(0xFFFFFFFFu, num, m);
    }
    if (lane == 0) out[row] = num / (den + 1e-16f) + __ldg(b2);
}

// --------------------------------------------------------------------------
extern "C" void kernel_launch(void* const* d_in, const int* in_sizes, int n_in,
                              void* d_out, int out_size) {
    const float* x     = (const float*)d_in[0];
    const int*   ei    = (const int*)d_in[1];
    const float* W1    = (const float*)d_in[2];
    const float* att_s = (const float*)d_in[3];
    const float* att_d = (const float*)d_in[4];
    const float* b1    = (const float*)d_in[5];
    const float* W2    = (const float*)d_in[6];
    const float* as2   = (const float*)d_in[7];
    const float* ad2   = (const float*)d_in[8];
    const float* b2    = (const float*)d_in[9];
    float* out = (float*)d_out;

    int N = in_sizes[0] / 16;
    int E = in_sizes[1] / 2;

    const int TB = 256;
    int nb_n  = (N + TB - 1) / TB;
    int nb_e  = (E + TB - 1) / TB;
    int nb_sc = (N + 1023) / 1024;        // scan blocks
    int nb_w  = (N + 7) / 8;              // warp-per-node blocks

    k_zero<<<nb_n, TB>>>(N);
    k_hist<<<nb_e, TB>>>(ei, E);
    k_node1<<<nb_n, TB>>>(x, W1, att_s, att_d, N);
    k_scan_block<<<nb_sc, 1024>>>(N);
    k_scan_top<<<1, 1024>>>(nb_sc);
    k_scan_add<<<nb_n, TB>>>(N);
    k_scatter<<<nb_e, TB>>>(ei, E);
    k_reduce1<<<nb_w, TB>>>(b1, W2, as2, ad2, N);
    k_reduce2<<<nb_w, TB>>>(out, as2, ad2, b2, N);
}

// round 5
// speedup vs baseline: 1.5419x; 1.0501x over previous
#include <cuda_runtime.h>
#include <cuda_fp16.h>

// GAT 2-layer, N<=100000, F_in=16, H=4, C=8. Atomic-free aggregation:
// per-call counting sort of edges by dst (CSR) + one-warp-per-dst reduction.
// Softmax without max-shift. h1 payload stored as packed fp16 (64B/row)
// to halve the dominant gather traffic in k_reduce1; logits stay fp32.

#define NMAX 100000
#define EMAX 3200000

__device__ uint2  g_h1h[NMAX * 8];  // h1 [N,32] as half2 pairs (row = 64B)
__device__ float4 g_as1[NMAX];      // a_src [N,4]
__device__ float4 g_ad1[NMAX];      // a_dst [N,4]
__device__ float  g_h2 [NMAX];
__device__ int    g_cnt[NMAX];      // in-degree
__device__ int    g_rs [NMAX];      // row start (exclusive scan of cnt)
__device__ int    g_ofs[NMAX];      // scatter cursor
__device__ int    g_src[EMAX];      // src ids grouped by dst
__device__ int    g_part[1024];     // scan partials

__device__ __forceinline__ float lrelu(float e) { return fmaxf(e, 0.2f * e); }

// --------------------------------------------------------------------------
__global__ void k_zero(int N) {
    int i = blockIdx.x * blockDim.x + threadIdx.x;
    if (i < N) g_cnt[i] = 0;
}

__global__ void k_hist(const int* __restrict__ ei, int E) {
    int i = blockIdx.x * blockDim.x + threadIdx.x;
    if (i < E) atomicAdd(&g_cnt[__ldg(ei + E + i)], 1);
}

// --------------------------------------------------------------------------
// Node features: h1 = x@W1 (fp32), logit halves as1/ad1 (fp32), pack h1->fp16
// --------------------------------------------------------------------------
__global__ void k_node1(const float* __restrict__ x, const float* __restrict__ W1,
                        const float* __restrict__ att_s, const float* __restrict__ att_d,
                        int N) {
    __shared__ float sW[512];
    __shared__ float sas[32], sad[32];
    for (int t = threadIdx.x; t < 512; t += blockDim.x) sW[t] = W1[t];
    if (threadIdx.x < 32) { sas[threadIdx.x] = att_s[threadIdx.x]; sad[threadIdx.x] = att_d[threadIdx.x]; }
    __syncthreads();

    int i = blockIdx.x * blockDim.x + threadIdx.x;
    if (i >= N) return;

    float xv[16];
    const float4* xr = reinterpret_cast<const float4*>(x + (size_t)i * 16);
    #pragma unroll
    for (int q = 0; q < 4; q++) {
        float4 v = xr[q];
        xv[4*q] = v.x; xv[4*q+1] = v.y; xv[4*q+2] = v.z; xv[4*q+3] = v.w;
    }

    float h[32];
    #pragma unroll
    for (int c = 0; c < 32; c++) h[c] = 0.f;
    #pragma unroll
    for (int k = 0; k < 16; k++) {
        float xk = xv[k];
        #pragma unroll
        for (int c = 0; c < 32; c++) h[c] = fmaf(xk, sW[k*32 + c], h[c]);
    }

    float as[4], ad[4];
    #pragma unroll
    for (int hh = 0; hh < 4; hh++) {
        float sa = 0.f, sd = 0.f;
        #pragma unroll
        for (int c = 0; c < 8; c++) {
            sa = fmaf(h[hh*8 + c], sas[hh*8 + c], sa);
            sd = fmaf(h[hh*8 + c], sad[hh*8 + c], sd);
        }
        as[hh] = sa; ad[hh] = sd;
    }

    #pragma unroll
    for (int q = 0; q < 8; q++) {
        half2 lo = __floats2half2_rn(h[4*q+0], h[4*q+1]);
        half2 hi = __floats2half2_rn(h[4*q+2], h[4*q+3]);
        uint2 p;
        p.x = *reinterpret_cast<unsigned*>(&lo);
        p.y = *reinterpret_cast<unsigned*>(&hi);
        g_h1h[(size_t)i * 8 + q] = p;
    }
    g_as1[i] = make_float4(as[0], as[1], as[2], as[3]);
    g_ad1[i] = make_float4(ad[0], ad[1], ad[2], ad[3]);
}

// --------------------------------------------------------------------------
// Two-level exclusive scan over g_cnt -> g_rs
// --------------------------------------------------------------------------
__global__ void k_scan_block(int N) {
    __shared__ int sh[1024];
    int t = threadIdx.x;
    int i = blockIdx.x * 1024 + t;
    int v = (i < N) ? g_cnt[i] : 0;
    sh[t] = v;
    __syncthreads();
    #pragma unroll
    for (int off = 1; off < 1024; off <<= 1) {
        int add = (t >= off) ? sh[t - off] : 0;
        __syncthreads();
        sh[t] += add;
        __syncthreads();
    }
    if (i < N) g_rs[i] = sh[t] - v;
    if (t == 1023) g_part[blockIdx.x] = sh[t];
}

__global__ void k_scan_top(int NB) {
    __shared__ int sh[1024];
    int t = threadIdx.x;
    int v = (t < NB) ? g_part[t] : 0;
    sh[t] = v;
    __syncthreads();
    #pragma unroll
    for (int off = 1; off < 1024; off <<= 1) {
        int add = (t >= off) ? sh[t - off] : 0;
        __syncthreads();
        sh[t] += add;
        __syncthreads();
    }
    if (t < NB) g_part[t] = sh[t] - v;
}

__global__ void k_scan_add(int N) {
    int i = blockIdx.x * blockDim.x + threadIdx.x;
    if (i >= N) return;
    int v = g_rs[i] + g_part[i >> 10];
    g_rs[i] = v;
    g_ofs[i] = v;
}

__global__ void k_scatter(const int* __restrict__ ei, int E) {
    int i = blockIdx.x * blockDim.x + threadIdx.x;
    if (i >= E) return;
    int s = __ldg(ei + i);
    int d = __ldg(ei + E + i);
    int pos = atomicAdd(&g_ofs[d], 1);
    g_src[pos] = s;
}

// --------------------------------------------------------------------------
// Layer-1 reduction + full node epilogue. One warp per dst node.
// Lane = 8*g + j: group g in [0,4) strides edges, lane j owns components
// [4j, 4j+4) (head = j>>1). h1 read as 8B packed-fp16 chunks (64B/row).
// --------------------------------------------------------------------------
__global__ void k_reduce1(const float* __restrict__ b1, const float* __restrict__ W2,
                          int N) {
    int warp = threadIdx.x >> 5;
    int row = blockIdx.x * 8 + warp;
    if (row >= N) return;
    int lane = threadIdx.x & 31;
    int j = lane & 7;
    int g = lane >> 3;
    int hsel = j >> 1;

    int rs = g_rs[row];
    int re = rs + g_cnt[row];
    float4 ad = g_ad1[row];

    float4 acc = make_float4(0.f, 0.f, 0.f, 0.f);
    float dsum = 0.f;

    if (g == 0) {  // self loop
        float4 as = g_as1[row];
        float ex0 = __expf(lrelu(as.x + ad.x));
        float ex1 = __expf(lrelu(as.y + ad.y));
        float ex2 = __expf(lrelu(as.z + ad.z));
        float ex3 = __expf(lrelu(as.w + ad.w));
        float e = hsel == 0 ? ex0 : hsel == 1 ? ex1 : hsel == 2 ? ex2 : ex3;
        uint2 p = g_h1h[(size_t)row * 8 + j];
        float2 lo = __half22float2(*reinterpret_cast<half2*>(&p.x));
        float2 hi = __half22float2(*reinterpret_cast<half2*>(&p.y));
        acc = make_float4(e*lo.x, e*lo.y, e*hi.x, e*hi.y);
        dsum = e;
    }

    for (int k = rs + g; k < re; k += 4) {
        int s = __ldg(&g_src[k]);
        float4 as = g_as1[s];
        float ex0 = __expf(lrelu(as.x + ad.x));
        float ex1 = __expf(lrelu(as.y + ad.y));
        float ex2 = __expf(lrelu(as.z + ad.z));
        float ex3 = __expf(lrelu(as.w + ad.w));
        float e = hsel == 0 ? ex0 : hsel == 1 ? ex1 : hsel == 2 ? ex2 : ex3;
        uint2 p = g_h1h[(size_t)s * 8 + j];
        float2 lo = __half22float2(*reinterpret_cast<half2*>(&p.x));
        float2 hi = __half22float2(*reinterpret_cast<half2*>(&p.y));
        acc.x = fmaf(e, lo.x, acc.x);
        acc.y = fmaf(e, lo.y, acc.y);
        acc.z = fmaf(e, hi.x, acc.z);
        acc.w = fmaf(e, hi.y, acc.w);
        dsum += e;
    }

    #pragma unroll
    for (int m = 8; m <= 16; m <<= 1) {
        acc.x += __shfl_xor_sync(0xFFFFFFFFu, acc.x, m);
        acc.y += __shfl_xor_sync(0xFFFFFFFFu, acc.y, m);
        acc.z += __shfl_xor_sync(0xFFFFFFFFu, acc.z, m);
        acc.w += __shfl_xor_sync(0xFFFFFFFFu, acc.w, m);
        dsum  += __shfl_xor_sync(0xFFFFFFFFu, dsum,  m);
    }

    // epilogue: normalize, +b1, elu, dot with W2
    float partial;
    {
        float id = 1.f / (dsum + 1e-16f);
        float o0 = acc.x * id + __ldg(b1 + 4*j + 0);
        float o1 = acc.y * id + __ldg(b1 + 4*j + 1);
        float o2 = acc.z * id + __ldg(b1 + 4*j + 2);
        float o3 = acc.w * id + __ldg(b1 + 4*j + 3);
        o0 = o0 > 0.f ? o0 : (__expf(o0) - 1.f);
        o1 = o1 > 0.f ? o1 : (__expf(o1) - 1.f);
        o2 = o2 > 0.f ? o2 : (__expf(o2) - 1.f);
        o3 = o3 > 0.f ? o3 : (__expf(o3) - 1.f);
        partial  = o0 * __ldg(W2 + 4*j + 0);
        partial += o1 * __ldg(W2 + 4*j + 1);
        partial += o2 * __ldg(W2 + 4*j + 2);
        partial += o3 * __ldg(W2 + 4*j + 3);
    }
    #pragma unroll
    for (int m = 1; m <= 4; m <<= 1)
        partial += __shfl_xor_sync(0xFFFFFFFFu, partial, m);

    if (lane == 0) g_h2[row] = partial;
}

// --------------------------------------------------------------------------
// Layer-2 reduction: one warp per dst, fused finalize.
// --------------------------------------------------------------------------
__global__ void k_reduce2(float* __restrict__ out,
                          const float* __restrict__ as2p, const float* __restrict__ ad2p,
                          const float* __restrict__ b2, int N) {
    int warp = threadIdx.x >> 5;
    int row = blockIdx.x * 8 + warp;
    if (row >= N) return;
    int lane = threadIdx.x & 31;

    float asc = __ldg(as2p), adc = __ldg(ad2p);
    float hd = g_h2[row];
    int rs = g_rs[row];
    int re = rs + g_cnt[row];

    float den = 0.f, num = 0.f;
    if (lane == 0) {  // self loop
        float ex = __expf(lrelu(hd * asc + hd * adc));
        den = ex; num = ex * hd;
    }
    for (int k = rs + lane; k < re; k += 32) {
        int s = __ldg(&g_src[k]);
        float hs = g_h2[s];
        float ex = __expf(lrelu(hs * asc + hd * adc));
        den += ex;
        num = fmaf(ex, hs, num);
    }
    #pragma unroll
    for (int m = 16; m >= 1; m >>= 1) {
        den += __shfl_xor_sync(0xFFFFFFFFu, den, m);
        num += __shfl_xor_sync(0xFFFFFFFFu, num, m);
    }
    if (lane == 0) out[row] = num / (den + 1e-16f) + __ldg(b2);
}

// --------------------------------------------------------------------------
extern "C" void kernel_launch(void* const* d_in, const int* in_sizes, int n_in,
                              void* d_out, int out_size) {
    const float* x     = (const float*)d_in[0];
    const int*   ei    = (const int*)d_in[1];
    const float* W1    = (const float*)d_in[2];
    const float* att_s = (const float*)d_in[3];
    const float* att_d = (const float*)d_in[4];
    const float* b1    = (const float*)d_in[5];
    const float* W2    = (const float*)d_in[6];
    const float* as2   = (const float*)d_in[7];
    const float* ad2   = (const float*)d_in[8];
    const float* b2    = (const float*)d_in[9];
    float* out = (float*)d_out;

    int N = in_sizes[0] / 16;
    int E = in_sizes[1] / 2;

    const int TB = 256;
    int nb_n  = (N + TB - 1) / TB;
    int nb_e  = (E + TB - 1) / TB;
    int nb_sc = (N + 1023) / 1024;
    int nb_w  = (N + 7) / 8;

    k_zero<<<nb_n, TB>>>(N);
    k_hist<<<nb_e, TB>>>(ei, E);
    k_node1<<<nb_n, TB>>>(x, W1, att_s, att_d, N);
    k_scan_block<<<nb_sc, 1024>>>(N);
    k_scan_top<<<1, 1024>>>(nb_sc);
    k_scan_add<<<nb_n, TB>>>(N);
    k_scatter<<<nb_e, TB>>>(ei, E);
    k_reduce1<<<nb_w, TB>>>(b1, W2, N);
    k_reduce2<<<nb_w, TB>>>(out, as2, ad2, b2, N);
}

// round 6
// speedup vs baseline: 1.9022x; 1.2336x over previous
#include <cuda_runtime.h>
#include <cuda_fp16.h>

// GAT 2-layer, N<=100000, F_in=16, H=4, C=8. Atomic-free aggregation:
// per-call counting sort of edges by dst (CSR) + one-warp-per-dst reduction.
// Softmax without max-shift. h1 stored as packed fp16 (64B/row).
// k_reduce1 edge loop software-pipelined (prefetch src idx) + 2x unrolled
// to double gather MLP (latency-bound loop).

#define NMAX 100000
#define EMAX 3200000

__device__ uint2  g_h1h[NMAX * 8];  // h1 [N,32] as half2 pairs (row = 64B)
__device__ float4 g_as1[NMAX];      // a_src [N,4]
__device__ float4 g_ad1[NMAX];      // a_dst [N,4]
__device__ float  g_h2 [NMAX];
__device__ int    g_cnt[NMAX];      // in-degree
__device__ int    g_rs [NMAX];      // row start
__device__ int    g_ofs[NMAX];      // scatter cursor
__device__ int    g_src[EMAX];      // src ids grouped by dst
__device__ int    g_part[1024];     // scan partials

__device__ __forceinline__ float lrelu(float e) { return fmaxf(e, 0.2f * e); }

// --------------------------------------------------------------------------
__global__ void k_zero(int N) {
    int i = blockIdx.x * blockDim.x + threadIdx.x;
    if (i < N) g_cnt[i] = 0;
}

__global__ void k_hist(const int* __restrict__ ei, int E) {
    int i = blockIdx.x * blockDim.x + threadIdx.x;
    if (i < E) atomicAdd(&g_cnt[__ldg(ei + E + i)], 1);
}

// --------------------------------------------------------------------------
__global__ void k_node1(const float* __restrict__ x, const float* __restrict__ W1,
                        const float* __restrict__ att_s, const float* __restrict__ att_d,
                        int N) {
    __shared__ float sW[512];
    __shared__ float sas[32], sad[32];
    for (int t = threadIdx.x; t < 512; t += blockDim.x) sW[t] = W1[t];
    if (threadIdx.x < 32) { sas[threadIdx.x] = att_s[threadIdx.x]; sad[threadIdx.x] = att_d[threadIdx.x]; }
    __syncthreads();

    int i = blockIdx.x * blockDim.x + threadIdx.x;
    if (i >= N) return;

    float xv[16];
    const float4* xr = reinterpret_cast<const float4*>(x + (size_t)i * 16);
    #pragma unroll
    for (int q = 0; q < 4; q++) {
        float4 v = xr[q];
        xv[4*q] = v.x; xv[4*q+1] = v.y; xv[4*q+2] = v.z; xv[4*q+3] = v.w;
    }

    float h[32];
    #pragma unroll
    for (int c = 0; c < 32; c++) h[c] = 0.f;
    #pragma unroll
    for (int k = 0; k < 16; k++) {
        float xk = xv[k];
        #pragma unroll
        for (int c = 0; c < 32; c++) h[c] = fmaf(xk, sW[k*32 + c], h[c]);
    }

    float as[4], ad[4];
    #pragma unroll
    for (int hh = 0; hh < 4; hh++) {
        float sa = 0.f, sd = 0.f;
        #pragma unroll
        for (int c = 0; c < 8; c++) {
            sa = fmaf(h[hh*8 + c], sas[hh*8 + c], sa);
            sd = fmaf(h[hh*8 + c], sad[hh*8 + c], sd);
        }
        as[hh] = sa; ad[hh] = sd;
    }

    #pragma unroll
    for (int q = 0; q < 8; q++) {
        half2 lo = __floats2half2_rn(h[4*q+0], h[4*q+1]);
        half2 hi = __floats2half2_rn(h[4*q+2], h[4*q+3]);
        uint2 p;
        p.x = *reinterpret_cast<unsigned*>(&lo);
        p.y = *reinterpret_cast<unsigned*>(&hi);
        g_h1h[(size_t)i * 8 + q] = p;
    }
    g_as1[i] = make_float4(as[0], as[1], as[2], as[3]);
    g_ad1[i] = make_float4(ad[0], ad[1], ad[2], ad[3]);
}

// --------------------------------------------------------------------------
__global__ void k_scan_block(int N) {
    __shared__ int sh[1024];
    int t = threadIdx.x;
    int i = blockIdx.x * 1024 + t;
    int v = (i < N) ? g_cnt[i] : 0;
    sh[t] = v;
    __syncthreads();
    #pragma unroll
    for (int off = 1; off < 1024; off <<= 1) {
        int add = (t >= off) ? sh[t - off] : 0;
        __syncthreads();
        sh[t] += add;
        __syncthreads();
    }
    if (i < N) g_rs[i] = sh[t] - v;
    if (t == 1023) g_part[blockIdx.x] = sh[t];
}

__global__ void k_scan_top(int NB) {
    __shared__ int sh[1024];
    int t = threadIdx.x;
    int v = (t < NB) ? g_part[t] : 0;
    sh[t] = v;
    __syncthreads();
    #pragma unroll
    for (int off = 1; off < 1024; off <<= 1) {
        int add = (t >= off) ? sh[t - off] : 0;
        __syncthreads();
        sh[t] += add;
        __syncthreads();
    }
    if (t < NB) g_part[t] = sh[t] - v;
}

__global__ void k_scan_add(int N) {
    int i = blockIdx.x * blockDim.x + threadIdx.x;
    if (i >= N) return;
    int v = g_rs[i] + g_part[i >> 10];
    g_rs[i] = v;
    g_ofs[i] = v;
}

__global__ void k_scatter(const int* __restrict__ ei, int E) {
    int i = blockIdx.x * blockDim.x + threadIdx.x;
    if (i >= E) return;
    int s = __ldg(ei + i);
    int d = __ldg(ei + E + i);
    int pos = atomicAdd(&g_ofs[d], 1);
    g_src[pos] = s;
}

// --------------------------------------------------------------------------
// Layer-1 reduction + full node epilogue. One warp per dst node.
// Lane = 8*g + j: group g strides edges, lane j owns components [4j,4j+4)
// (head = j>>1). Edge loop: prefetch-pipelined, 2 edges per group per iter.
// --------------------------------------------------------------------------
__global__ void k_reduce1(const float* __restrict__ b1, const float* __restrict__ W2,
                          int N) {
    int warp = threadIdx.x >> 5;
    int row = blockIdx.x * 8 + warp;
    if (row >= N) return;
    int lane = threadIdx.x & 31;
    int j = lane & 7;
    int g = lane >> 3;
    int hsel = j >> 1;

    int rs = g_rs[row];
    int re = rs + g_cnt[row];
    float4 ad = g_ad1[row];
    float adh = hsel == 0 ? ad.x : hsel == 1 ? ad.y : hsel == 2 ? ad.z : ad.w;

    float4 acc = make_float4(0.f, 0.f, 0.f, 0.f);
    float dsum = 0.f;

    if (g == 0) {  // self loop
        float4 as = g_as1[row];
        float ash = hsel == 0 ? as.x : hsel == 1 ? as.y : hsel == 2 ? as.z : as.w;
        float e = __expf(lrelu(ash + adh));
        uint2 p = g_h1h[(size_t)row * 8 + j];
        float2 lo = __half22float2(*reinterpret_cast<half2*>(&p.x));
        float2 hi = __half22float2(*reinterpret_cast<half2*>(&p.y));
        acc = make_float4(e*lo.x, e*lo.y, e*hi.x, e*hi.y);
        dsum = e;
    }

    int k = rs + g;
    int s0 = (k     < re) ? __ldg(&g_src[k])     : 0;
    int s1 = (k + 4 < re) ? __ldg(&g_src[k + 4]) : 0;

    while (k + 4 < re) {
        int s2 = (k + 8  < re) ? __ldg(&g_src[k + 8])  : 0;
        int s3 = (k + 12 < re) ? __ldg(&g_src[k + 12]) : 0;

        float4 asA = g_as1[s0];
        uint2  pA  = g_h1h[(size_t)s0 * 8 + j];
        float4 asB = g_as1[s1];
        uint2  pB  = g_h1h[(size_t)s1 * 8 + j];

        float ashA = hsel == 0 ? asA.x : hsel == 1 ? asA.y : hsel == 2 ? asA.z : asA.w;
        float eA = __expf(lrelu(ashA + adh));
        float2 loA = __half22float2(*reinterpret_cast<half2*>(&pA.x));
        float2 hiA = __half22float2(*reinterpret_cast<half2*>(&pA.y));
        acc.x = fmaf(eA, loA.x, acc.x);
        acc.y = fmaf(eA, loA.y, acc.y);
        acc.z = fmaf(eA, hiA.x, acc.z);
        acc.w = fmaf(eA, hiA.y, acc.w);
        dsum += eA;

        float ashB = hsel == 0 ? asB.x : hsel == 1 ? asB.y : hsel == 2 ? asB.z : asB.w;
        float eB = __expf(lrelu(ashB + adh));
        float2 loB = __half22float2(*reinterpret_cast<half2*>(&pB.x));
        float2 hiB = __half22float2(*reinterpret_cast<half2*>(&pB.y));
        acc.x = fmaf(eB, loB.x, acc.x);
        acc.y = fmaf(eB, loB.y, acc.y);
        acc.z = fmaf(eB, hiB.x, acc.z);
        acc.w = fmaf(eB, hiB.y, acc.w);
        dsum += eB;

        s0 = s2; s1 = s3; k += 8;
    }
    if (k < re) {  // one trailing edge for this group
        float4 asA = g_as1[s0];
        uint2  pA  = g_h1h[(size_t)s0 * 8 + j];
        float ashA = hsel == 0 ? asA.x : hsel == 1 ? asA.y : hsel == 2 ? asA.z : asA.w;
        float eA = __expf(lrelu(ashA + adh));
        float2 loA = __half22float2(*reinterpret_cast<half2*>(&pA.x));
        float2 hiA = __half22float2(*reinterpret_cast<half2*>(&pA.y));
        acc.x = fmaf(eA, loA.x, acc.x);
        acc.y = fmaf(eA, loA.y, acc.y);
        acc.z = fmaf(eA, hiA.x, acc.z);
        acc.w = fmaf(eA, hiA.y, acc.w);
        dsum += eA;
    }

    #pragma unroll
    for (int m = 8; m <= 16; m <<= 1) {
        acc.x += __shfl_xor_sync(0xFFFFFFFFu, acc.x, m);
        acc.y += __shfl_xor_sync(0xFFFFFFFFu, acc.y, m);
        acc.z += __shfl_xor_sync(0xFFFFFFFFu, acc.z, m);
        acc.w += __shfl_xor_sync(0xFFFFFFFFu, acc.w, m);
        dsum  += __shfl_xor_sync(0xFFFFFFFFu, dsum,  m);
    }

    // epilogue: normalize, +b1, elu, dot with W2
    float partial;
    {
        float id = 1.f / (dsum + 1e-16f);
        float o0 = acc.x * id + __ldg(b1 + 4*j + 0);
        float o1 = acc.y * id + __ldg(b1 + 4*j + 1);
        float o2 = acc.z * id + __ldg(b1 + 4*j + 2);
        float o3 = acc.w * id + __ldg(b1 + 4*j + 3);
        o0 = o0 > 0.f ? o0 : (__expf(o0) - 1.f);
        o1 = o1 > 0.f ? o1 : (__expf(o1) - 1.f);
        o2 = o2 > 0.f ? o2 : (__expf(o2) - 1.f);
        o3 = o3 > 0.f ? o3 : (__expf(o3) - 1.f);
        partial  = o0 * __ldg(W2 + 4*j + 0);
        partial += o1 * __ldg(W2 + 4*j + 1);
        partial += o2 * __ldg(W2 + 4*j + 2);
        partial += o3 * __ldg(W2 + 4*j + 3);
    }
    #pragma unroll
    for (int m = 1; m <= 4; m <<= 1)
        partial += __shfl_xor_sync(0xFFFFFFFFu, partial, m);

    if (lane == 0) g_h2[row] = partial;
}

// --------------------------------------------------------------------------
__global__ void k_reduce2(float* __restrict__ out,
                          const float* __restrict__ as2p, const float* __restrict__ ad2p,
                          const float* __restrict__ b2, int N) {
    int warp = threadIdx.x >> 5;
    int row = blockIdx.x * 8 + warp;
    if (row >= N) return;
    int lane = threadIdx.x & 31;

    float asc = __ldg(as2p), adc = __ldg(ad2p);
    float hd = g_h2[row];
    int rs = g_rs[row];
    int re = rs + g_cnt[row];

    float den = 0.f, num = 0.f;
    if (lane == 0) {  // self loop
        float ex = __expf(lrelu(hd * asc + hd * adc));
        den = ex; num = ex * hd;
    }
    for (int k = rs + lane; k < re; k += 32) {
        int s = __ldg(&g_src[k]);
        float hs = g_h2[s];
        float ex = __expf(lrelu(hs * asc + hd * adc));
        den += ex;
        num = fmaf(ex, hs, num);
    }
    #pragma unroll
    for (int m = 16; m >= 1; m >>= 1) {
        den += __shfl_xor_sync(0xFFFFFFFFu, den, m);
        num += __shfl_xor_sync(0xFFFFFFFFu, num, m);
    }
    if (lane == 0) out[row] = num / (den + 1e-16f) + __ldg(b2);
}

// --------------------------------------------------------------------------
extern "C" void kernel_launch(void* const* d_in, const int* in_sizes, int n_in,
                              void* d_out, int out_size) {
    const float* x     = (const float*)d_in[0];
    const int*   ei    = (const int*)d_in[1];
    const float* W1    = (const float*)d_in[2];
    const float* att_s = (const float*)d_in[3];
    const float* att_d = (const float*)d_in[4];
    const float* b1    = (const float*)d_in[5];
    const float* W2    = (const float*)d_in[6];
    const float* as2   = (const float*)d_in[7];
    const float* ad2   = (const float*)d_in[8];
    const float* b2    = (const float*)d_in[9];
    float* out = (float*)d_out;

    int N = in_sizes[0] / 16;
    int E = in_sizes[1] / 2;

    const int TB = 256;
    int nb_n  = (N + TB - 1) / TB;
    int nb_e  = (E + TB - 1) / TB;
    int nb_sc = (N + 1023) / 1024;
    int nb_w  = (N + 7) / 8;

    k_zero<<<nb_n, TB>>>(N);
    k_hist<<<nb_e, TB>>>(ei, E);
    k_node1<<<nb_n, TB>>>(x, W1, att_s, att_d, N);
    k_scan_block<<<nb_sc, 1024>>>(N);
    k_scan_top<<<1, 1024>>>(nb_sc);
    k_scan_add<<<nb_n, TB>>>(N);
    k_scatter<<<nb_e, TB>>>(ei, E);
    k_reduce1<<<nb_w, TB>>>(b1, W2, N);
    k_reduce2<<<nb_w, TB>>>(out, as2, ad2, b2, N);
}